// round 7
// baseline (speedup 1.0000x reference)
#include <cuda_runtime.h>
#include <cuda_bf16.h>
#include <math.h>
#include <stdint.h>

// Problem shape (fixed)
#define BBATCH 8
#define QQ 1024
#define KK 4096
#define HH 512
#define OUT_ELEMS (BBATCH * QQ * HH)

// Scratch
__device__ float g_mix[(size_t)BBATCH * QQ * HH];               // 16 MB
__device__ __nv_bfloat16 g_ctxT_hi[(size_t)BBATCH * HH * KK];   // 32 MB  [b][h][k]
__device__ __nv_bfloat16 g_ctxT_lo[(size_t)BBATCH * HH * KK];   // 32 MB

// ---------------------------------------------------------------------------
// helpers
// ---------------------------------------------------------------------------
__device__ __forceinline__ uint32_t smem_u32(const void* p) {
    uint32_t a;
    asm("{ .reg .u64 t; cvta.to.shared.u64 t, %1; cvt.u32.u64 %0, t; }" : "=r"(a) : "l"(p));
    return a;
}

__device__ __forceinline__ void ldsm4(uint32_t* r, uint32_t addr) {
    asm volatile("ldmatrix.sync.aligned.m8n8.x4.shared.b16 {%0,%1,%2,%3}, [%4];"
                 : "=r"(r[0]), "=r"(r[1]), "=r"(r[2]), "=r"(r[3]) : "r"(addr));
}
__device__ __forceinline__ void mma_bf16(float* c, const uint32_t* a, const uint32_t* b) {
    asm volatile(
        "mma.sync.aligned.m16n8k16.row.col.f32.bf16.bf16.f32 "
        "{%0,%1,%2,%3}, {%4,%5,%6,%7}, {%8,%9}, {%0,%1,%2,%3};"
        : "+f"(c[0]), "+f"(c[1]), "+f"(c[2]), "+f"(c[3])
        : "r"(a[0]), "r"(a[1]), "r"(a[2]), "r"(a[3]), "r"(b[0]), "r"(b[1]));
}

// fp32 float4 -> hi/lo bf16 packed
__device__ __forceinline__ void split4(float4 v, uint2& ph, uint2& pl) {
    __nv_bfloat16 h0 = __float2bfloat16_rn(v.x);
    __nv_bfloat16 h1 = __float2bfloat16_rn(v.y);
    __nv_bfloat16 h2 = __float2bfloat16_rn(v.z);
    __nv_bfloat16 h3 = __float2bfloat16_rn(v.w);
    __nv_bfloat16 l0 = __float2bfloat16_rn(v.x - __bfloat162float(h0));
    __nv_bfloat16 l1 = __float2bfloat16_rn(v.y - __bfloat162float(h1));
    __nv_bfloat16 l2 = __float2bfloat16_rn(v.z - __bfloat162float(h2));
    __nv_bfloat16 l3 = __float2bfloat16_rn(v.w - __bfloat162float(h3));
    ph.x = (uint32_t)__bfloat16_as_ushort(h0) | ((uint32_t)__bfloat16_as_ushort(h1) << 16);
    ph.y = (uint32_t)__bfloat16_as_ushort(h2) | ((uint32_t)__bfloat16_as_ushort(h3) << 16);
    pl.x = (uint32_t)__bfloat16_as_ushort(l0) | ((uint32_t)__bfloat16_as_ushort(l1) << 16);
    pl.y = (uint32_t)__bfloat16_as_ushort(l2) | ((uint32_t)__bfloat16_as_ushort(l3) << 16);
}

// SMEM tile: 128 rows x 32 cols bf16, padded stride 40 elements (80 B)
#define TSTRIDE 40
#define ARR_B (128 * TSTRIDE * 2)        // bytes per array (10240)
#define STAGE_B (4 * ARR_B)              // Ah, Al, Bh, Bl    (40960)
#define SMEM_TOTAL (2 * STAGE_B)         // double buffered   (81920)

// ---------------------------------------------------------------------------
// Unified bf16x3 NT GEMM: C[m][n] = sum_k A[m][k] * B[n][k]
// MODE 0: scores (+mask->-inf)   1: mix   2: out (+bias, tanh)
// CTA tile 128x128, 256 threads (8 warps: 4 M x 2 N), K chunk 32.
// Register prefetch + double-buffered smem (1 barrier/chunk); 2 CTAs/SM.
// ---------------------------------------------------------------------------
template <int MODE>
__global__ __launch_bounds__(256, 2) void gemm_kernel(
    const float* __restrict__ outp, const float* __restrict__ ctx,
    const int* __restrict__ mask, const float* __restrict__ W,
    const float* __restrict__ bias, float* __restrict__ attn,
    float* __restrict__ mixp, float* __restrict__ outpart,
    const __nv_bfloat16* __restrict__ ctxT_hi, const __nv_bfloat16* __restrict__ ctxT_lo)
{
    extern __shared__ __align__(16) char smem[];

    const int t = threadIdx.x, wid = t >> 5, lid = t & 31;
    const int wx = wid & 1;      // N: 2 x 64
    const int wy = wid >> 1;     // M: 4 x 32
    const int b = blockIdx.z, q0 = blockIdx.y * 128, n0 = blockIdx.x * 128;
    const int KLEN = (MODE == 0) ? HH : (MODE == 1) ? KK : 2 * HH;
    const int NCH = KLEN / 32;

    // load coordinates (fp32 conv path): 4 x (row, col4)
    const int cr[4] = { (t + 0) >> 3, (t + 256) >> 3, (t + 512) >> 3, (t + 768) >> 3 };
    const int cc    = (t & 7) << 2;
    // bf16 copy path (MODE 1 B): 2 x (row, col8)
    const int br2[2] = { t >> 2, (t + 256) >> 2 };
    const int bc2    = (t & 3) << 3;

    float acc[2][8][4];
    #pragma unroll
    for (int mt = 0; mt < 2; mt++)
        #pragma unroll
        for (int nt = 0; nt < 8; nt++)
            #pragma unroll
            for (int j = 0; j < 4; j++) acc[mt][nt][j] = 0.f;

    const uint32_t sbase = smem_u32(smem);
    const int lane16 = lid & 15;

    // prefetch registers
    float4 fa[4];
    float4 fb[4];
    uint4  vh[2], vl[2];

    auto load_chunk = [&](int ch) {
        const int k0 = ch * 32;
        const float* asrc;
        if (MODE == 0)      asrc = outp + ((size_t)(b * QQ + q0)) * HH + k0;
        else if (MODE == 1) asrc = attn + ((size_t)(b * QQ + q0)) * KK + k0;
        else asrc = (k0 < HH) ? (mixp + ((size_t)(b * QQ + q0)) * HH + k0)
                              : (outp + ((size_t)(b * QQ + q0)) * HH + (k0 - HH));
        const int astr = (MODE == 1) ? KK : HH;
        #pragma unroll
        for (int u = 0; u < 4; u++)
            fa[u] = *(const float4*)(asrc + (size_t)cr[u] * astr + cc);
        if (MODE == 1) {
            const __nv_bfloat16* sh = ctxT_hi + ((size_t)(b * HH + n0)) * KK + k0;
            const __nv_bfloat16* sl = ctxT_lo + ((size_t)(b * HH + n0)) * KK + k0;
            #pragma unroll
            for (int u = 0; u < 2; u++) {
                vh[u] = *(const uint4*)(sh + (size_t)br2[u] * KK + bc2);
                vl[u] = *(const uint4*)(sl + (size_t)br2[u] * KK + bc2);
            }
        } else {
            const float* bsrc = (MODE == 0)
                ? (ctx + ((size_t)(b * KK + n0)) * HH + k0)
                : (W + (size_t)n0 * (2 * HH) + k0);
            const int bstr = (MODE == 0) ? HH : 2 * HH;
            #pragma unroll
            for (int u = 0; u < 4; u++)
                fb[u] = *(const float4*)(bsrc + (size_t)cr[u] * bstr + cc);
        }
    };

    auto store_chunk = [&](int stage) {
        char* base = smem + stage * STAGE_B;
        uint16_t* Ah = (uint16_t*)(base);
        uint16_t* Al = (uint16_t*)(base + ARR_B);
        uint16_t* Bh = (uint16_t*)(base + 2 * ARR_B);
        uint16_t* Bl = (uint16_t*)(base + 3 * ARR_B);
        #pragma unroll
        for (int u = 0; u < 4; u++) {
            uint2 ph, pl;
            split4(fa[u], ph, pl);
            *(uint2*)(Ah + cr[u] * TSTRIDE + cc) = ph;
            *(uint2*)(Al + cr[u] * TSTRIDE + cc) = pl;
        }
        if (MODE == 1) {
            #pragma unroll
            for (int u = 0; u < 2; u++) {
                *(uint4*)(Bh + br2[u] * TSTRIDE + bc2) = vh[u];
                *(uint4*)(Bl + br2[u] * TSTRIDE + bc2) = vl[u];
            }
        } else {
            #pragma unroll
            for (int u = 0; u < 4; u++) {
                uint2 ph, pl;
                split4(fb[u], ph, pl);
                *(uint2*)(Bh + cr[u] * TSTRIDE + cc) = ph;
                *(uint2*)(Bl + cr[u] * TSTRIDE + cc) = pl;
            }
        }
    };

    load_chunk(0);
    store_chunk(0);
    __syncthreads();

    for (int ch = 0; ch < NCH; ch++) {
        const int cur = ch & 1;
        if (ch + 1 < NCH) load_chunk(ch + 1);   // gmem loads overlap MMAs

        const uint32_t sAh = sbase + cur * STAGE_B;
        const uint32_t sAl = sAh + ARR_B;
        const uint32_t sBh = sAh + 2 * ARR_B;
        const uint32_t sBl = sAh + 3 * ARR_B;

        #pragma unroll
        for (int kt = 0; kt < 2; kt++) {
            uint32_t afh[2][4], afl[2][4];
            #pragma unroll
            for (int mt = 0; mt < 2; mt++) {
                uint32_t off = (uint32_t)((wy * 32 + mt * 16 + lane16) * (TSTRIDE * 2)
                                          + kt * 32 + ((lid >> 4) << 4));
                ldsm4(afh[mt], sAh + off);
                ldsm4(afl[mt], sAl + off);
            }
            // B: x4 ldmatrix covers n16 x k16 (two n8 frags at once)
            #pragma unroll
            for (int np = 0; np < 4; np++) {
                const int brow = wx * 64 + np * 16 + ((lid & 16) >> 1) + (lid & 7);
                uint32_t boff = (uint32_t)(brow * (TSTRIDE * 2)
                                           + kt * 32 + (((lid >> 3) & 1) << 4));
                uint32_t bfh[4], bfl[4];
                ldsm4(bfh, sBh + boff);
                ldsm4(bfl, sBl + boff);
                #pragma unroll
                for (int half = 0; half < 2; half++) {
                    const int nt = np * 2 + half;
                    #pragma unroll
                    for (int mt = 0; mt < 2; mt++) {
                        mma_bf16(acc[mt][nt], afh[mt], bfh + half * 2);
                        mma_bf16(acc[mt][nt], afh[mt], bfl + half * 2);
                        mma_bf16(acc[mt][nt], afl[mt], bfh + half * 2);
                    }
                }
            }
        }
        if (ch + 1 < NCH) store_chunk((ch + 1) & 1);
        __syncthreads();
    }

    // ---- epilogue ----
    const int rq = lid >> 2;          // 0..7
    const int cq = (lid & 3) * 2;     // 0,2,4,6
    #pragma unroll
    for (int mt = 0; mt < 2; mt++) {
        #pragma unroll
        for (int nt = 0; nt < 8; nt++) {
            const int col = n0 + wx * 64 + nt * 8 + cq;
            #pragma unroll
            for (int half = 0; half < 2; half++) {
                const int row = q0 + wy * 32 + mt * 16 + rq + half * 8;
                float v0 = acc[mt][nt][half * 2 + 0];
                float v1 = acc[mt][nt][half * 2 + 1];
                if (MODE == 0) {
                    const size_t o = ((size_t)(b * QQ + row)) * KK + col;
                    int2 mk = *(const int2*)(mask + o);
                    float2 w2;
                    w2.x = mk.x ? -INFINITY : v0;
                    w2.y = mk.y ? -INFINITY : v1;
                    *(float2*)(attn + o) = w2;
                } else if (MODE == 1) {
                    const size_t o = ((size_t)(b * QQ + row)) * HH + col;
                    *(float2*)(mixp + o) = make_float2(v0, v1);
                } else {
                    const size_t o = ((size_t)(b * QQ + row)) * HH + col;
                    float2 bi = *(const float2*)(bias + col);
                    *(float2*)(outpart + o) = make_float2(tanhf(v0 + bi.x), tanhf(v1 + bi.y));
                }
            }
        }
    }
}

// ---------------------------------------------------------------------------
// Transpose + split: ctx[b][k][h] (fp32) -> ctxT_hi/lo[b][h][k] (bf16)
// ---------------------------------------------------------------------------
__global__ __launch_bounds__(256) void transpose_split_kernel(
    const float* __restrict__ ctx, __nv_bfloat16* __restrict__ th,
    __nv_bfloat16* __restrict__ tl)
{
    __shared__ float tile[32][33];
    const int b = blockIdx.z, k0 = blockIdx.x * 32, h0 = blockIdx.y * 32;
    const int t = threadIdx.x;
    const int tx = t & 31, ty = t >> 5;
    const float* src = ctx + ((size_t)(b * KK + k0)) * HH + h0;
    #pragma unroll
    for (int j = ty; j < 32; j += 8) tile[j][tx] = src[(size_t)j * HH + tx];
    __syncthreads();
    const int h  = t >> 3;         // 0..31
    const int p0 = t & 7;          // 0..7
    #pragma unroll
    for (int s = 0; s < 2; s++) {
        const int p = p0 + s * 8;          // 0..15
        float v0 = tile[2 * p + 0][h];
        float v1 = tile[2 * p + 1][h];
        __nv_bfloat16 h0b = __float2bfloat16_rn(v0);
        __nv_bfloat16 h1b = __float2bfloat16_rn(v1);
        __nv_bfloat16 l0b = __float2bfloat16_rn(v0 - __bfloat162float(h0b));
        __nv_bfloat16 l1b = __float2bfloat16_rn(v1 - __bfloat162float(h1b));
        uint32_t ph = (uint32_t)__bfloat16_as_ushort(h0b) | ((uint32_t)__bfloat16_as_ushort(h1b) << 16);
        uint32_t pl = (uint32_t)__bfloat16_as_ushort(l0b) | ((uint32_t)__bfloat16_as_ushort(l1b) << 16);
        size_t o = ((size_t)(b * HH + h0 + h)) * KK + k0 + 2 * p;
        *(uint32_t*)(th + o) = ph;
        *(uint32_t*)(tl + o) = pl;
    }
}

// ---------------------------------------------------------------------------
// Softmax: one CTA per row, register resident (256 thr x 16 floats)
// ---------------------------------------------------------------------------
__global__ __launch_bounds__(256) void softmax_kernel(float* __restrict__ attn)
{
    const size_t row = blockIdx.x;
    float4* p = (float4*)(attn + row * KK);
    const int t = threadIdx.x, wid = t >> 5, lid = t & 31;
    __shared__ float red[8];

    float4 v[4];
    float mx = -INFINITY;
    #pragma unroll
    for (int j = 0; j < 4; j++) {
        v[j] = p[t + j * 256];
        mx = fmaxf(mx, fmaxf(fmaxf(v[j].x, v[j].y), fmaxf(v[j].z, v[j].w)));
    }
    #pragma unroll
    for (int s = 16; s > 0; s >>= 1) mx = fmaxf(mx, __shfl_xor_sync(0xffffffffu, mx, s));
    if (lid == 0) red[wid] = mx;
    __syncthreads();
    float m2 = red[0];
    #pragma unroll
    for (int i = 1; i < 8; i++) m2 = fmaxf(m2, red[i]);
    __syncthreads();

    float sum = 0.f;
    #pragma unroll
    for (int j = 0; j < 4; j++) {
        v[j].x = __expf(v[j].x - m2);
        v[j].y = __expf(v[j].y - m2);
        v[j].z = __expf(v[j].z - m2);
        v[j].w = __expf(v[j].w - m2);
        sum += v[j].x + v[j].y + v[j].z + v[j].w;
    }
    #pragma unroll
    for (int s = 16; s > 0; s >>= 1) sum += __shfl_xor_sync(0xffffffffu, sum, s);
    if (lid == 0) red[wid] = sum;
    __syncthreads();
    float tot = 0.f;
    #pragma unroll
    for (int i = 0; i < 8; i++) tot += red[i];
    const float inv = 1.f / tot;

    #pragma unroll
    for (int j = 0; j < 4; j++) {
        v[j].x *= inv; v[j].y *= inv; v[j].z *= inv; v[j].w *= inv;
        p[t + j * 256] = v[j];
    }
}

// ---------------------------------------------------------------------------
extern "C" void kernel_launch(void* const* d_in, const int* in_sizes, int n_in,
                              void* d_out, int out_size)
{
    const float* outp = (const float*)d_in[0];   // [B,Q,H]
    const float* ctx  = (const float*)d_in[1];   // [B,K,H]
    const int*   mask = (const int*)d_in[2];     // [B,Q,K] (bool->int32)
    const float* W    = (const float*)d_in[3];   // [H,2H]
    const float* bias = (const float*)d_in[4];   // [H]

    float* out_part  = (float*)d_out;
    float* attn_part = (float*)d_out + OUT_ELEMS;

    float* mixp;
    __nv_bfloat16 *th, *tl;
    cudaGetSymbolAddress((void**)&mixp, g_mix);
    cudaGetSymbolAddress((void**)&th, g_ctxT_hi);
    cudaGetSymbolAddress((void**)&tl, g_ctxT_lo);

    cudaFuncSetAttribute(gemm_kernel<0>, cudaFuncAttributeMaxDynamicSharedMemorySize, SMEM_TOTAL);
    cudaFuncSetAttribute(gemm_kernel<1>, cudaFuncAttributeMaxDynamicSharedMemorySize, SMEM_TOTAL);
    cudaFuncSetAttribute(gemm_kernel<2>, cudaFuncAttributeMaxDynamicSharedMemorySize, SMEM_TOTAL);

    // ctx transpose + split (for mix's B operand)
    {
        dim3 grid(KK / 32, HH / 32, BBATCH);
        transpose_split_kernel<<<grid, 256>>>(ctx, th, tl);
    }
    // scores (+mask) -> attn region
    {
        dim3 grid(KK / 128, QQ / 128, BBATCH);
        gemm_kernel<0><<<grid, 256, SMEM_TOTAL>>>(outp, ctx, mask, W, bias,
                                                  attn_part, mixp, out_part, th, tl);
    }
    // softmax in place
    softmax_kernel<<<BBATCH * QQ, 256>>>(attn_part);
    // mix = attn @ ctx
    {
        dim3 grid(HH / 128, QQ / 128, BBATCH);
        gemm_kernel<1><<<grid, 256, SMEM_TOTAL>>>(outp, ctx, mask, W, bias,
                                                  attn_part, mixp, out_part, th, tl);
    }
    // out = tanh([mix|output] @ W^T + b)
    {
        dim3 grid(HH / 128, QQ / 128, BBATCH);
        gemm_kernel<2><<<grid, 256, SMEM_TOTAL>>>(outp, ctx, mask, W, bias,
                                                  attn_part, mixp, out_part, th, tl);
    }
}

// round 8
// speedup vs baseline: 1.0516x; 1.0516x over previous
#include <cuda_runtime.h>
#include <cuda_bf16.h>
#include <math.h>
#include <stdint.h>

// Problem shape (fixed)
#define BBATCH 8
#define QQ 1024
#define KK 4096
#define HH 512
#define OUT_ELEMS (BBATCH * QQ * HH)

// Scratch
__device__ float g_mix[(size_t)BBATCH * QQ * HH];               // 16 MB
__device__ __nv_bfloat16 g_ctxT_hi[(size_t)BBATCH * HH * KK];   // 32 MB  [b][h][k]
__device__ __nv_bfloat16 g_ctxT_lo[(size_t)BBATCH * HH * KK];   // 32 MB

// ---------------------------------------------------------------------------
// helpers
// ---------------------------------------------------------------------------
__device__ __forceinline__ uint32_t smem_u32(const void* p) {
    uint32_t a;
    asm("{ .reg .u64 t; cvta.to.shared.u64 t, %1; cvt.u32.u64 %0, t; }" : "=r"(a) : "l"(p));
    return a;
}

__device__ __forceinline__ void ldsm4(uint32_t* r, uint32_t addr) {
    asm volatile("ldmatrix.sync.aligned.m8n8.x4.shared.b16 {%0,%1,%2,%3}, [%4];"
                 : "=r"(r[0]), "=r"(r[1]), "=r"(r[2]), "=r"(r[3]) : "r"(addr));
}
__device__ __forceinline__ void ldsm2(uint32_t* r, uint32_t addr) {
    asm volatile("ldmatrix.sync.aligned.m8n8.x2.shared.b16 {%0,%1}, [%2];"
                 : "=r"(r[0]), "=r"(r[1]) : "r"(addr));
}
__device__ __forceinline__ void mma_bf16(float* c, const uint32_t* a, const uint32_t* b) {
    asm volatile(
        "mma.sync.aligned.m16n8k16.row.col.f32.bf16.bf16.f32 "
        "{%0,%1,%2,%3}, {%4,%5,%6,%7}, {%8,%9}, {%0,%1,%2,%3};"
        : "+f"(c[0]), "+f"(c[1]), "+f"(c[2]), "+f"(c[3])
        : "r"(a[0]), "r"(a[1]), "r"(a[2]), "r"(a[3]), "r"(b[0]), "r"(b[1]));
}

// fp32 float4 -> hi/lo bf16 packed
__device__ __forceinline__ void split4(float4 v, uint2& ph, uint2& pl) {
    __nv_bfloat16 h0 = __float2bfloat16_rn(v.x);
    __nv_bfloat16 h1 = __float2bfloat16_rn(v.y);
    __nv_bfloat16 h2 = __float2bfloat16_rn(v.z);
    __nv_bfloat16 h3 = __float2bfloat16_rn(v.w);
    __nv_bfloat16 l0 = __float2bfloat16_rn(v.x - __bfloat162float(h0));
    __nv_bfloat16 l1 = __float2bfloat16_rn(v.y - __bfloat162float(h1));
    __nv_bfloat16 l2 = __float2bfloat16_rn(v.z - __bfloat162float(h2));
    __nv_bfloat16 l3 = __float2bfloat16_rn(v.w - __bfloat162float(h3));
    ph.x = (uint32_t)__bfloat16_as_ushort(h0) | ((uint32_t)__bfloat16_as_ushort(h1) << 16);
    ph.y = (uint32_t)__bfloat16_as_ushort(h2) | ((uint32_t)__bfloat16_as_ushort(h3) << 16);
    pl.x = (uint32_t)__bfloat16_as_ushort(l0) | ((uint32_t)__bfloat16_as_ushort(l1) << 16);
    pl.y = (uint32_t)__bfloat16_as_ushort(l2) | ((uint32_t)__bfloat16_as_ushort(l3) << 16);
}

// SMEM tile: 128 rows x 32 cols bf16, padded stride 40 elements (80 B)
#define TSTRIDE 40

// ---------------------------------------------------------------------------
// Unified bf16x3 NT GEMM: C[m][n] = sum_k A[m][k] * B[n][k]
// MODE 0: scores (+mask->-inf)   1: mix   2: out (+bias, tanh)
// CTA tile 128x128, 256 threads (8 warps: 4 M x 2 N), K chunk 32.
// Register-prefetch pipeline; 2 CTAs/SM.  Term-major MMA schedule
// (breaks accumulator RAW chains between the 3 split-product MMAs).
// ---------------------------------------------------------------------------
template <int MODE>
__global__ __launch_bounds__(256, 2) void gemm_kernel(
    const float* __restrict__ outp, const float* __restrict__ ctx,
    const int* __restrict__ mask, const float* __restrict__ W,
    const float* __restrict__ bias, float* __restrict__ attn,
    float* __restrict__ mixp, float* __restrict__ outpart,
    const __nv_bfloat16* __restrict__ ctxT_hi, const __nv_bfloat16* __restrict__ ctxT_lo)
{
    __shared__ __align__(16) uint16_t Ah[128 * TSTRIDE];
    __shared__ __align__(16) uint16_t Al[128 * TSTRIDE];
    __shared__ __align__(16) uint16_t Bh[128 * TSTRIDE];
    __shared__ __align__(16) uint16_t Bl[128 * TSTRIDE];

    const int t = threadIdx.x, wid = t >> 5, lid = t & 31;
    const int wx = wid & 1;      // N: 2 x 64
    const int wy = wid >> 1;     // M: 4 x 32
    const int b = blockIdx.z, q0 = blockIdx.y * 128, n0 = blockIdx.x * 128;
    const int KLEN = (MODE == 0) ? HH : (MODE == 1) ? KK : 2 * HH;
    const int NCH = KLEN / 32;

    // load coordinates (fp32 conv path): 4 x (row, col4)
    const int cr[4] = { (t + 0) >> 3, (t + 256) >> 3, (t + 512) >> 3, (t + 768) >> 3 };
    const int cc    = (t & 7) << 2;
    // bf16 copy path (MODE 1 B): 2 x (row, col8)
    const int br2[2] = { t >> 2, (t + 256) >> 2 };
    const int bc2    = (t & 3) << 3;

    float acc[2][8][4];
    #pragma unroll
    for (int mt = 0; mt < 2; mt++)
        #pragma unroll
        for (int nt = 0; nt < 8; nt++)
            #pragma unroll
            for (int j = 0; j < 4; j++) acc[mt][nt][j] = 0.f;

    const uint32_t sAh = smem_u32(Ah), sAl = smem_u32(Al);
    const uint32_t sBh = smem_u32(Bh), sBl = smem_u32(Bl);
    const int lane16 = lid & 15;

    // prefetch registers
    float4 fa[4];
    float4 fb[4];
    uint4  vh[2], vl[2];

    auto load_chunk = [&](int ch) {
        const int k0 = ch * 32;
        const float* asrc;
        if (MODE == 0)      asrc = outp + ((size_t)(b * QQ + q0)) * HH + k0;
        else if (MODE == 1) asrc = attn + ((size_t)(b * QQ + q0)) * KK + k0;
        else asrc = (k0 < HH) ? (mixp + ((size_t)(b * QQ + q0)) * HH + k0)
                              : (outp + ((size_t)(b * QQ + q0)) * HH + (k0 - HH));
        const int astr = (MODE == 1) ? KK : HH;
        #pragma unroll
        for (int u = 0; u < 4; u++)
            fa[u] = *(const float4*)(asrc + (size_t)cr[u] * astr + cc);
        if (MODE == 1) {
            const __nv_bfloat16* sh = ctxT_hi + ((size_t)(b * HH + n0)) * KK + k0;
            const __nv_bfloat16* sl = ctxT_lo + ((size_t)(b * HH + n0)) * KK + k0;
            #pragma unroll
            for (int u = 0; u < 2; u++) {
                vh[u] = *(const uint4*)(sh + (size_t)br2[u] * KK + bc2);
                vl[u] = *(const uint4*)(sl + (size_t)br2[u] * KK + bc2);
            }
        } else {
            const float* bsrc = (MODE == 0)
                ? (ctx + ((size_t)(b * KK + n0)) * HH + k0)
                : (W + (size_t)n0 * (2 * HH) + k0);
            const int bstr = (MODE == 0) ? HH : 2 * HH;
            #pragma unroll
            for (int u = 0; u < 4; u++)
                fb[u] = *(const float4*)(bsrc + (size_t)cr[u] * bstr + cc);
        }
    };

    auto store_chunk = [&]() {
        #pragma unroll
        for (int u = 0; u < 4; u++) {
            uint2 ph, pl;
            split4(fa[u], ph, pl);
            *(uint2*)(Ah + cr[u] * TSTRIDE + cc) = ph;
            *(uint2*)(Al + cr[u] * TSTRIDE + cc) = pl;
        }
        if (MODE == 1) {
            #pragma unroll
            for (int u = 0; u < 2; u++) {
                *(uint4*)(Bh + br2[u] * TSTRIDE + bc2) = vh[u];
                *(uint4*)(Bl + br2[u] * TSTRIDE + bc2) = vl[u];
            }
        } else {
            #pragma unroll
            for (int u = 0; u < 4; u++) {
                uint2 ph, pl;
                split4(fb[u], ph, pl);
                *(uint2*)(Bh + cr[u] * TSTRIDE + cc) = ph;
                *(uint2*)(Bl + cr[u] * TSTRIDE + cc) = pl;
            }
        }
    };

    load_chunk(0);
    store_chunk();
    __syncthreads();

    for (int ch = 0; ch < NCH; ch++) {
        if (ch + 1 < NCH) load_chunk(ch + 1);   // gmem loads overlap MMAs below

        #pragma unroll
        for (int kt = 0; kt < 2; kt++) {
            uint32_t afh[2][4], afl[2][4];
            #pragma unroll
            for (int mt = 0; mt < 2; mt++) {
                uint32_t off = (uint32_t)((wy * 32 + mt * 16 + lane16) * (TSTRIDE * 2)
                                          + kt * 32 + ((lid >> 4) << 4));
                ldsm4(afh[mt], sAh + off);
                ldsm4(afl[mt], sAl + off);
            }
            // process nt in pairs; term-major schedule inside each pair so that
            // same-accumulator MMAs are 4 apart (RAW chain broken)
            #pragma unroll
            for (int np = 0; np < 4; np++) {
                const int nt0 = np * 2, nt1 = np * 2 + 1;
                uint32_t b0off = (uint32_t)((wx * 64 + nt0 * 8 + (lane16 & 7)) * (TSTRIDE * 2)
                                            + kt * 32 + (((lane16 >> 3) & 1) << 4));
                uint32_t b1off = (uint32_t)((wx * 64 + nt1 * 8 + (lane16 & 7)) * (TSTRIDE * 2)
                                            + kt * 32 + (((lane16 >> 3) & 1) << 4));
                uint32_t bh0[2], bh1[2], bl0[2], bl1[2];
                ldsm2(bh0, sBh + b0off);
                ldsm2(bh1, sBh + b1off);
                ldsm2(bl0, sBl + b0off);
                ldsm2(bl1, sBl + b1off);
                // term hh
                mma_bf16(acc[0][nt0], afh[0], bh0);
                mma_bf16(acc[0][nt1], afh[0], bh1);
                mma_bf16(acc[1][nt0], afh[1], bh0);
                mma_bf16(acc[1][nt1], afh[1], bh1);
                // term hl
                mma_bf16(acc[0][nt0], afh[0], bl0);
                mma_bf16(acc[0][nt1], afh[0], bl1);
                mma_bf16(acc[1][nt0], afh[1], bl0);
                mma_bf16(acc[1][nt1], afh[1], bl1);
                // term lh
                mma_bf16(acc[0][nt0], afl[0], bh0);
                mma_bf16(acc[0][nt1], afl[0], bh1);
                mma_bf16(acc[1][nt0], afl[1], bh0);
                mma_bf16(acc[1][nt1], afl[1], bh1);
            }
        }
        __syncthreads();
        if (ch + 1 < NCH) {
            store_chunk();
            __syncthreads();
        }
    }

    // ---- epilogue ----
    const int rq = lid >> 2;          // 0..7
    const int cq = (lid & 3) * 2;     // 0,2,4,6
    #pragma unroll
    for (int mt = 0; mt < 2; mt++) {
        #pragma unroll
        for (int nt = 0; nt < 8; nt++) {
            const int col = n0 + wx * 64 + nt * 8 + cq;
            #pragma unroll
            for (int half = 0; half < 2; half++) {
                const int row = q0 + wy * 32 + mt * 16 + rq + half * 8;
                float v0 = acc[mt][nt][half * 2 + 0];
                float v1 = acc[mt][nt][half * 2 + 1];
                if (MODE == 0) {
                    const size_t o = ((size_t)(b * QQ + row)) * KK + col;
                    int2 mk = *(const int2*)(mask + o);
                    float2 w2;
                    w2.x = mk.x ? -INFINITY : v0;
                    w2.y = mk.y ? -INFINITY : v1;
                    *(float2*)(attn + o) = w2;
                } else if (MODE == 1) {
                    const size_t o = ((size_t)(b * QQ + row)) * HH + col;
                    *(float2*)(mixp + o) = make_float2(v0, v1);
                } else {
                    const size_t o = ((size_t)(b * QQ + row)) * HH + col;
                    float2 bi = *(const float2*)(bias + col);
                    *(float2*)(outpart + o) = make_float2(tanhf(v0 + bi.x), tanhf(v1 + bi.y));
                }
            }
        }
    }
}

// ---------------------------------------------------------------------------
// Transpose + split: ctx[b][k][h] (fp32) -> ctxT_hi/lo[b][h][k] (bf16)
// ---------------------------------------------------------------------------
__global__ __launch_bounds__(256) void transpose_split_kernel(
    const float* __restrict__ ctx, __nv_bfloat16* __restrict__ th,
    __nv_bfloat16* __restrict__ tl)
{
    __shared__ float tile[32][33];
    const int b = blockIdx.z, k0 = blockIdx.x * 32, h0 = blockIdx.y * 32;
    const int t = threadIdx.x;
    const int tx = t & 31, ty = t >> 5;
    const float* src = ctx + ((size_t)(b * KK + k0)) * HH + h0;
    #pragma unroll
    for (int j = ty; j < 32; j += 8) tile[j][tx] = src[(size_t)j * HH + tx];
    __syncthreads();
    const int h  = t >> 3;         // 0..31
    const int p0 = t & 7;          // 0..7
    #pragma unroll
    for (int s = 0; s < 2; s++) {
        const int p = p0 + s * 8;          // 0..15
        float v0 = tile[2 * p + 0][h];
        float v1 = tile[2 * p + 1][h];
        __nv_bfloat16 h0b = __float2bfloat16_rn(v0);
        __nv_bfloat16 h1b = __float2bfloat16_rn(v1);
        __nv_bfloat16 l0b = __float2bfloat16_rn(v0 - __bfloat162float(h0b));
        __nv_bfloat16 l1b = __float2bfloat16_rn(v1 - __bfloat162float(h1b));
        uint32_t ph = (uint32_t)__bfloat16_as_ushort(h0b) | ((uint32_t)__bfloat16_as_ushort(h1b) << 16);
        uint32_t pl = (uint32_t)__bfloat16_as_ushort(l0b) | ((uint32_t)__bfloat16_as_ushort(l1b) << 16);
        size_t o = ((size_t)(b * HH + h0 + h)) * KK + k0 + 2 * p;
        *(uint32_t*)(th + o) = ph;
        *(uint32_t*)(tl + o) = pl;
    }
}

// ---------------------------------------------------------------------------
// Softmax: one CTA per row, register resident (256 thr x 16 floats)
// ---------------------------------------------------------------------------
__global__ __launch_bounds__(256) void softmax_kernel(float* __restrict__ attn)
{
    const size_t row = blockIdx.x;
    float4* p = (float4*)(attn + row * KK);
    const int t = threadIdx.x, wid = t >> 5, lid = t & 31;
    __shared__ float red[8];

    float4 v[4];
    float mx = -INFINITY;
    #pragma unroll
    for (int j = 0; j < 4; j++) {
        v[j] = p[t + j * 256];
        mx = fmaxf(mx, fmaxf(fmaxf(v[j].x, v[j].y), fmaxf(v[j].z, v[j].w)));
    }
    #pragma unroll
    for (int s = 16; s > 0; s >>= 1) mx = fmaxf(mx, __shfl_xor_sync(0xffffffffu, mx, s));
    if (lid == 0) red[wid] = mx;
    __syncthreads();
    float m2 = red[0];
    #pragma unroll
    for (int i = 1; i < 8; i++) m2 = fmaxf(m2, red[i]);
    __syncthreads();

    float sum = 0.f;
    #pragma unroll
    for (int j = 0; j < 4; j++) {
        v[j].x = __expf(v[j].x - m2);
        v[j].y = __expf(v[j].y - m2);
        v[j].z = __expf(v[j].z - m2);
        v[j].w = __expf(v[j].w - m2);
        sum += v[j].x + v[j].y + v[j].z + v[j].w;
    }
    #pragma unroll
    for (int s = 16; s > 0; s >>= 1) sum += __shfl_xor_sync(0xffffffffu, sum, s);
    if (lid == 0) red[wid] = sum;
    __syncthreads();
    float tot = 0.f;
    #pragma unroll
    for (int i = 0; i < 8; i++) tot += red[i];
    const float inv = 1.f / tot;

    #pragma unroll
    for (int j = 0; j < 4; j++) {
        v[j].x *= inv; v[j].y *= inv; v[j].z *= inv; v[j].w *= inv;
        p[t + j * 256] = v[j];
    }
}

// ---------------------------------------------------------------------------
extern "C" void kernel_launch(void* const* d_in, const int* in_sizes, int n_in,
                              void* d_out, int out_size)
{
    const float* outp = (const float*)d_in[0];   // [B,Q,H]
    const float* ctx  = (const float*)d_in[1];   // [B,K,H]
    const int*   mask = (const int*)d_in[2];     // [B,Q,K] (bool->int32)
    const float* W    = (const float*)d_in[3];   // [H,2H]
    const float* bias = (const float*)d_in[4];   // [H]

    float* out_part  = (float*)d_out;
    float* attn_part = (float*)d_out + OUT_ELEMS;

    float* mixp;
    __nv_bfloat16 *th, *tl;
    cudaGetSymbolAddress((void**)&mixp, g_mix);
    cudaGetSymbolAddress((void**)&th, g_ctxT_hi);
    cudaGetSymbolAddress((void**)&tl, g_ctxT_lo);

    // ctx transpose + split (for mix's B operand)
    {
        dim3 grid(KK / 32, HH / 32, BBATCH);
        transpose_split_kernel<<<grid, 256>>>(ctx, th, tl);
    }
    // scores (+mask) -> attn region
    {
        dim3 grid(KK / 128, QQ / 128, BBATCH);
        gemm_kernel<0><<<grid, 256>>>(outp, ctx, mask, W, bias,
                                      attn_part, mixp, out_part, th, tl);
    }
    // softmax in place
    softmax_kernel<<<BBATCH * QQ, 256>>>(attn_part);
    // mix = attn @ ctx
    {
        dim3 grid(HH / 128, QQ / 128, BBATCH);
        gemm_kernel<1><<<grid, 256>>>(outp, ctx, mask, W, bias,
                                      attn_part, mixp, out_part, th, tl);
    }
    // out = tanh([mix|output] @ W^T + b)
    {
        dim3 grid(HH / 128, QQ / 128, BBATCH);
        gemm_kernel<2><<<grid, 256>>>(outp, ctx, mask, W, bias,
                                      attn_part, mixp, out_part, th, tl);
    }
}

// round 9
// speedup vs baseline: 1.0891x; 1.0357x over previous
#include <cuda_runtime.h>
#include <cuda_bf16.h>
#include <math.h>
#include <stdint.h>

// Problem shape (fixed)
#define BBATCH 8
#define QQ 1024
#define KK 4096
#define HH 512
#define OUT_ELEMS (BBATCH * QQ * HH)

// Pre-split bf16 operands (hi/lo) in gmem
__device__ __nv_bfloat16 g_outp_hi[(size_t)BBATCH * QQ * HH];
__device__ __nv_bfloat16 g_outp_lo[(size_t)BBATCH * QQ * HH];
__device__ __nv_bfloat16 g_ctx_hi [(size_t)BBATCH * KK * HH];   // [b][k][h]
__device__ __nv_bfloat16 g_ctx_lo [(size_t)BBATCH * KK * HH];
__device__ __nv_bfloat16 g_ctxT_hi[(size_t)BBATCH * HH * KK];   // [b][h][k]
__device__ __nv_bfloat16 g_ctxT_lo[(size_t)BBATCH * HH * KK];
__device__ __nv_bfloat16 g_attn_hi[(size_t)BBATCH * QQ * KK];
__device__ __nv_bfloat16 g_attn_lo[(size_t)BBATCH * QQ * KK];
__device__ __nv_bfloat16 g_mix_hi [(size_t)BBATCH * QQ * HH];
__device__ __nv_bfloat16 g_mix_lo [(size_t)BBATCH * QQ * HH];
__device__ __nv_bfloat16 g_W_hi   [(size_t)HH * 2 * HH];
__device__ __nv_bfloat16 g_W_lo   [(size_t)HH * 2 * HH];

// ---------------------------------------------------------------------------
// helpers
// ---------------------------------------------------------------------------
__device__ __forceinline__ uint32_t smem_u32(const void* p) {
    uint32_t a;
    asm("{ .reg .u64 t; cvta.to.shared.u64 t, %1; cvt.u32.u64 %0, t; }" : "=r"(a) : "l"(p));
    return a;
}
__device__ __forceinline__ void ldsm4(uint32_t* r, uint32_t addr) {
    asm volatile("ldmatrix.sync.aligned.m8n8.x4.shared.b16 {%0,%1,%2,%3}, [%4];"
                 : "=r"(r[0]), "=r"(r[1]), "=r"(r[2]), "=r"(r[3]) : "r"(addr));
}
__device__ __forceinline__ void mma_bf16(float* c, const uint32_t* a, const uint32_t* b) {
    asm volatile(
        "mma.sync.aligned.m16n8k16.row.col.f32.bf16.bf16.f32 "
        "{%0,%1,%2,%3}, {%4,%5,%6,%7}, {%8,%9}, {%0,%1,%2,%3};"
        : "+f"(c[0]), "+f"(c[1]), "+f"(c[2]), "+f"(c[3])
        : "r"(a[0]), "r"(a[1]), "r"(a[2]), "r"(a[3]), "r"(b[0]), "r"(b[1]));
}
__device__ __forceinline__ void cp16(uint32_t dst, const void* src) {
    asm volatile("cp.async.cg.shared.global [%0], [%1], 16;" :: "r"(dst), "l"(src));
}
#define CP_COMMIT() asm volatile("cp.async.commit_group;" ::: "memory")
#define CP_WAIT0()  asm volatile("cp.async.wait_group 0;" ::: "memory")

// fp32 float4 -> hi/lo bf16 packed
__device__ __forceinline__ void split4(float4 v, uint2& ph, uint2& pl) {
    __nv_bfloat16 h0 = __float2bfloat16_rn(v.x);
    __nv_bfloat16 h1 = __float2bfloat16_rn(v.y);
    __nv_bfloat16 h2 = __float2bfloat16_rn(v.z);
    __nv_bfloat16 h3 = __float2bfloat16_rn(v.w);
    __nv_bfloat16 l0 = __float2bfloat16_rn(v.x - __bfloat162float(h0));
    __nv_bfloat16 l1 = __float2bfloat16_rn(v.y - __bfloat162float(h1));
    __nv_bfloat16 l2 = __float2bfloat16_rn(v.z - __bfloat162float(h2));
    __nv_bfloat16 l3 = __float2bfloat16_rn(v.w - __bfloat162float(h3));
    ph.x = (uint32_t)__bfloat16_as_ushort(h0) | ((uint32_t)__bfloat16_as_ushort(h1) << 16);
    ph.y = (uint32_t)__bfloat16_as_ushort(h2) | ((uint32_t)__bfloat16_as_ushort(h3) << 16);
    pl.x = (uint32_t)__bfloat16_as_ushort(l0) | ((uint32_t)__bfloat16_as_ushort(l1) << 16);
    pl.y = (uint32_t)__bfloat16_as_ushort(l2) | ((uint32_t)__bfloat16_as_ushort(l3) << 16);
}

// SMEM: rows of 80 bytes (64B data + 16B pad). Arrays: Ah, Al, Bh, Bl.
#define ROWB   80
#define ARR_B  (128 * ROWB)          // 10240 B
#define STAGE_B (4 * ARR_B)          // 40960 B
#define SMEM_TOTAL (2 * STAGE_B)     // 81920 B

// ---------------------------------------------------------------------------
// Pure-bf16 hi/lo NT GEMM: C[m][n] = sum_k A[m][k]*B[n][k] (3-term split)
// MODE 0: scores (+mask)  1: mix (emit hi/lo)  2: out (+bias, tanh)
// CTA 128x128, 4 warps (2Mx2N, warp tile 64x64), K chunk 32, cp.async 2-stage.
// ---------------------------------------------------------------------------
template <int MODE>
__global__ __launch_bounds__(128, 2) void gemm_kernel(
    const __nv_bfloat16* __restrict__ A1h, const __nv_bfloat16* __restrict__ A1l,
    const __nv_bfloat16* __restrict__ A2h, const __nv_bfloat16* __restrict__ A2l,
    const __nv_bfloat16* __restrict__ Bhg, const __nv_bfloat16* __restrict__ Blg,
    const int* __restrict__ mask, const float* __restrict__ bias,
    float* __restrict__ attn, __nv_bfloat16* __restrict__ mixh,
    __nv_bfloat16* __restrict__ mixl, float* __restrict__ outpart)
{
    extern __shared__ __align__(16) char smem[];
    const uint32_t sbase = smem_u32(smem);

    const int t = threadIdx.x, wid = t >> 5, lid = t & 31;
    const int wx = wid & 1;       // N: 2 x 64
    const int wy = wid >> 1;      // M: 2 x 64
    const int b = blockIdx.z, q0 = blockIdx.y * 128, n0 = blockIdx.x * 128;
    const int KLEN = (MODE == 0) ? HH : (MODE == 1) ? KK : 2 * HH;
    const int NCH = KLEN / 32;
    const int lda = (MODE == 1) ? KK : HH;     // A row stride (elements)
    const int ldb = (MODE == 0) ? HH : (MODE == 1) ? KK : 2 * HH;

    float acc[4][8][4];
    #pragma unroll
    for (int mt = 0; mt < 4; mt++)
        #pragma unroll
        for (int nt = 0; nt < 8; nt++)
            #pragma unroll
            for (int j = 0; j < 4; j++) acc[mt][nt][j] = 0.f;

    // cp.async coords: idx = t + i*128 -> row = idx>>2 (0..127), cu = idx&3 (16B unit)
    const int lrow[4] = { (t + 0) >> 2, (t + 128) >> 2, (t + 256) >> 2, (t + 384) >> 2 };
    const int lcu    = (t & 3) << 3;       // element offset (8 bf16 = 16B)

    auto issue_chunk = [&](int ch, int st) {
        const int k0 = ch * 32;
        const __nv_bfloat16 *ah, *al;
        int ak0;
        if (MODE == 2 && k0 >= HH) { ah = A2h; al = A2l; ak0 = k0 - HH; }
        else                       { ah = A1h; al = A1l; ak0 = k0; }
        const __nv_bfloat16* arow_h = ah + ((size_t)(b * QQ + q0)) * lda + ak0;
        const __nv_bfloat16* arow_l = al + ((size_t)(b * QQ + q0)) * lda + ak0;
        const size_t bbase = (MODE == 2) ? ((size_t)n0 * ldb + k0)
                                         : (((size_t)(b * (MODE == 0 ? KK : HH) + n0)) * ldb + k0);
        const __nv_bfloat16* brow_h = Bhg + bbase;
        const __nv_bfloat16* brow_l = Blg + bbase;
        const uint32_t sb = sbase + st * STAGE_B;
        #pragma unroll
        for (int i = 0; i < 4; i++) {
            const uint32_t doff = (uint32_t)(lrow[i] * ROWB + (lcu << 1));
            cp16(sb + doff,              arow_h + (size_t)lrow[i] * lda + lcu);
            cp16(sb + ARR_B + doff,      arow_l + (size_t)lrow[i] * lda + lcu);
            cp16(sb + 2 * ARR_B + doff,  brow_h + (size_t)lrow[i] * ldb + lcu);
            cp16(sb + 3 * ARR_B + doff,  brow_l + (size_t)lrow[i] * ldb + lcu);
        }
        CP_COMMIT();
    };

    const int lane16 = lid & 15;

    issue_chunk(0, 0);

    for (int ch = 0; ch < NCH; ch++) {
        CP_WAIT0();
        __syncthreads();
        if (ch + 1 < NCH) issue_chunk(ch + 1, (ch + 1) & 1);

        const uint32_t sb  = sbase + (ch & 1) * STAGE_B;
        const uint32_t sAh = sb, sAl = sb + ARR_B, sBh = sb + 2 * ARR_B, sBl = sb + 3 * ARR_B;

        #pragma unroll
        for (int kt = 0; kt < 2; kt++) {
            uint32_t afh[4][4], afl[4][4];
            #pragma unroll
            for (int mt = 0; mt < 4; mt++) {
                uint32_t off = (uint32_t)((wy * 64 + mt * 16 + lane16) * ROWB
                                          + kt * 32 + ((lid >> 4) << 4));
                ldsm4(afh[mt], sAh + off);
                ldsm4(afl[mt], sAl + off);
            }
            #pragma unroll
            for (int np = 0; np < 4; np++) {
                const int nt0 = np * 2, nt1 = np * 2 + 1;
                const int brow = wx * 64 + np * 16 + ((lid & 16) >> 1) + (lid & 7);
                uint32_t boff = (uint32_t)(brow * ROWB + kt * 32 + (((lid >> 3) & 1) << 4));
                uint32_t bh[4], bl[4];
                ldsm4(bh, sBh + boff);
                ldsm4(bl, sBl + boff);
                // term hh (8 MMAs), hl (8), lh (8): same-acc revisit distance = 8
                #pragma unroll
                for (int mt = 0; mt < 4; mt++) {
                    mma_bf16(acc[mt][nt0], afh[mt], bh);
                    mma_bf16(acc[mt][nt1], afh[mt], bh + 2);
                }
                #pragma unroll
                for (int mt = 0; mt < 4; mt++) {
                    mma_bf16(acc[mt][nt0], afh[mt], bl);
                    mma_bf16(acc[mt][nt1], afh[mt], bl + 2);
                }
                #pragma unroll
                for (int mt = 0; mt < 4; mt++) {
                    mma_bf16(acc[mt][nt0], afl[mt], bh);
                    mma_bf16(acc[mt][nt1], afl[mt], bh + 2);
                }
            }
        }
        __syncthreads();
    }

    // ---- epilogue ----
    const int rq = lid >> 2;          // 0..7
    const int cq = (lid & 3) * 2;     // 0,2,4,6
    #pragma unroll
    for (int mt = 0; mt < 4; mt++) {
        #pragma unroll
        for (int nt = 0; nt < 8; nt++) {
            const int col = n0 + wx * 64 + nt * 8 + cq;
            #pragma unroll
            for (int half = 0; half < 2; half++) {
                const int row = q0 + wy * 64 + mt * 16 + rq + half * 8;
                float v0 = acc[mt][nt][half * 2 + 0];
                float v1 = acc[mt][nt][half * 2 + 1];
                if (MODE == 0) {
                    const size_t o = ((size_t)(b * QQ + row)) * KK + col;
                    int2 mk = *(const int2*)(mask + o);
                    float2 w2;
                    w2.x = mk.x ? -INFINITY : v0;
                    w2.y = mk.y ? -INFINITY : v1;
                    *(float2*)(attn + o) = w2;
                } else if (MODE == 1) {
                    const size_t o = ((size_t)(b * QQ + row)) * HH + col;
                    __nv_bfloat16 h0 = __float2bfloat16_rn(v0);
                    __nv_bfloat16 h1 = __float2bfloat16_rn(v1);
                    __nv_bfloat16 l0 = __float2bfloat16_rn(v0 - __bfloat162float(h0));
                    __nv_bfloat16 l1 = __float2bfloat16_rn(v1 - __bfloat162float(h1));
                    uint32_t ph = (uint32_t)__bfloat16_as_ushort(h0) | ((uint32_t)__bfloat16_as_ushort(h1) << 16);
                    uint32_t pl = (uint32_t)__bfloat16_as_ushort(l0) | ((uint32_t)__bfloat16_as_ushort(l1) << 16);
                    *(uint32_t*)(mixh + o) = ph;
                    *(uint32_t*)(mixl + o) = pl;
                } else {
                    const size_t o = ((size_t)(b * QQ + row)) * HH + col;
                    float2 bi = *(const float2*)(bias + col);
                    *(float2*)(outpart + o) = make_float2(tanhf(v0 + bi.x), tanhf(v1 + bi.y));
                }
            }
        }
    }
}

// ---------------------------------------------------------------------------
// Generic fp32 -> hi/lo bf16 split (vectorized, memory-bound)
// ---------------------------------------------------------------------------
__global__ __launch_bounds__(256) void split_kernel(
    const float* __restrict__ src, __nv_bfloat16* __restrict__ hi,
    __nv_bfloat16* __restrict__ lo, size_t n4)
{
    size_t i = (size_t)blockIdx.x * 256 + threadIdx.x;
    if (i >= n4) return;
    float4 v = *(const float4*)(src + i * 4);
    uint2 ph, pl;
    split4(v, ph, pl);
    *(uint2*)(hi + i * 4) = ph;
    *(uint2*)(lo + i * 4) = pl;
}

// ---------------------------------------------------------------------------
// Transpose + split: ctx[b][k][h] (fp32) -> ctxT_hi/lo[b][h][k] (bf16)
// ---------------------------------------------------------------------------
__global__ __launch_bounds__(256) void transpose_split_kernel(
    const float* __restrict__ ctx, __nv_bfloat16* __restrict__ th,
    __nv_bfloat16* __restrict__ tl)
{
    __shared__ float tile[32][33];
    const int b = blockIdx.z, k0 = blockIdx.x * 32, h0 = blockIdx.y * 32;
    const int t = threadIdx.x;
    const int tx = t & 31, ty = t >> 5;
    const float* src = ctx + ((size_t)(b * KK + k0)) * HH + h0;
    #pragma unroll
    for (int j = ty; j < 32; j += 8) tile[j][tx] = src[(size_t)j * HH + tx];
    __syncthreads();
    const int h  = t >> 3;         // 0..31
    const int p0 = t & 7;          // 0..7
    #pragma unroll
    for (int s = 0; s < 2; s++) {
        const int p = p0 + s * 8;          // 0..15
        float v0 = tile[2 * p + 0][h];
        float v1 = tile[2 * p + 1][h];
        __nv_bfloat16 h0b = __float2bfloat16_rn(v0);
        __nv_bfloat16 h1b = __float2bfloat16_rn(v1);
        __nv_bfloat16 l0b = __float2bfloat16_rn(v0 - __bfloat162float(h0b));
        __nv_bfloat16 l1b = __float2bfloat16_rn(v1 - __bfloat162float(h1b));
        uint32_t ph = (uint32_t)__bfloat16_as_ushort(h0b) | ((uint32_t)__bfloat16_as_ushort(h1b) << 16);
        uint32_t pl = (uint32_t)__bfloat16_as_ushort(l0b) | ((uint32_t)__bfloat16_as_ushort(l1b) << 16);
        size_t o = ((size_t)(b * HH + h0 + h)) * KK + k0 + 2 * p;
        *(uint32_t*)(th + o) = ph;
        *(uint32_t*)(tl + o) = pl;
    }
}

// ---------------------------------------------------------------------------
// Softmax: one CTA/row, register resident; emits fp32 attn + hi/lo bf16
// ---------------------------------------------------------------------------
__global__ __launch_bounds__(256) void softmax_kernel(
    float* __restrict__ attn, __nv_bfloat16* __restrict__ ah,
    __nv_bfloat16* __restrict__ al)
{
    const size_t row = blockIdx.x;
    float4* p = (float4*)(attn + row * KK);
    const int t = threadIdx.x, wid = t >> 5, lid = t & 31;
    __shared__ float red[8];

    float4 v[4];
    float mx = -INFINITY;
    #pragma unroll
    for (int j = 0; j < 4; j++) {
        v[j] = p[t + j * 256];
        mx = fmaxf(mx, fmaxf(fmaxf(v[j].x, v[j].y), fmaxf(v[j].z, v[j].w)));
    }
    #pragma unroll
    for (int s = 16; s > 0; s >>= 1) mx = fmaxf(mx, __shfl_xor_sync(0xffffffffu, mx, s));
    if (lid == 0) red[wid] = mx;
    __syncthreads();
    float m2 = red[0];
    #pragma unroll
    for (int i = 1; i < 8; i++) m2 = fmaxf(m2, red[i]);
    __syncthreads();

    float sum = 0.f;
    #pragma unroll
    for (int j = 0; j < 4; j++) {
        v[j].x = __expf(v[j].x - m2);
        v[j].y = __expf(v[j].y - m2);
        v[j].z = __expf(v[j].z - m2);
        v[j].w = __expf(v[j].w - m2);
        sum += v[j].x + v[j].y + v[j].z + v[j].w;
    }
    #pragma unroll
    for (int s = 16; s > 0; s >>= 1) sum += __shfl_xor_sync(0xffffffffu, sum, s);
    if (lid == 0) red[wid] = sum;
    __syncthreads();
    float tot = 0.f;
    #pragma unroll
    for (int i = 0; i < 8; i++) tot += red[i];
    const float inv = 1.f / tot;

    __nv_bfloat16* hrow = ah + row * KK;
    __nv_bfloat16* lrow = al + row * KK;
    #pragma unroll
    for (int j = 0; j < 4; j++) {
        v[j].x *= inv; v[j].y *= inv; v[j].z *= inv; v[j].w *= inv;
        p[t + j * 256] = v[j];
        uint2 ph, pl;
        split4(v[j], ph, pl);
        *(uint2*)(hrow + (size_t)(t + j * 256) * 4) = ph;
        *(uint2*)(lrow + (size_t)(t + j * 256) * 4) = pl;
    }
}

// ---------------------------------------------------------------------------
extern "C" void kernel_launch(void* const* d_in, const int* in_sizes, int n_in,
                              void* d_out, int out_size)
{
    const float* outp = (const float*)d_in[0];   // [B,Q,H]
    const float* ctx  = (const float*)d_in[1];   // [B,K,H]
    const int*   mask = (const int*)d_in[2];     // [B,Q,K]
    const float* W    = (const float*)d_in[3];   // [H,2H]
    const float* bias = (const float*)d_in[4];   // [H]

    float* out_part  = (float*)d_out;
    float* attn_part = (float*)d_out + OUT_ELEMS;

    __nv_bfloat16 *oh, *ol, *ch, *cl, *cth, *ctl, *ath, *atl, *mh, *ml, *wh, *wl;
    cudaGetSymbolAddress((void**)&oh,  g_outp_hi);
    cudaGetSymbolAddress((void**)&ol,  g_outp_lo);
    cudaGetSymbolAddress((void**)&ch,  g_ctx_hi);
    cudaGetSymbolAddress((void**)&cl,  g_ctx_lo);
    cudaGetSymbolAddress((void**)&cth, g_ctxT_hi);
    cudaGetSymbolAddress((void**)&ctl, g_ctxT_lo);
    cudaGetSymbolAddress((void**)&ath, g_attn_hi);
    cudaGetSymbolAddress((void**)&atl, g_attn_lo);
    cudaGetSymbolAddress((void**)&mh,  g_mix_hi);
    cudaGetSymbolAddress((void**)&ml,  g_mix_lo);
    cudaGetSymbolAddress((void**)&wh,  g_W_hi);
    cudaGetSymbolAddress((void**)&wl,  g_W_lo);

    cudaFuncSetAttribute(gemm_kernel<0>, cudaFuncAttributeMaxDynamicSharedMemorySize, SMEM_TOTAL);
    cudaFuncSetAttribute(gemm_kernel<1>, cudaFuncAttributeMaxDynamicSharedMemorySize, SMEM_TOTAL);
    cudaFuncSetAttribute(gemm_kernel<2>, cudaFuncAttributeMaxDynamicSharedMemorySize, SMEM_TOTAL);

    // Pre-split passes
    {
        size_t n4;
        n4 = (size_t)BBATCH * QQ * HH / 4;
        split_kernel<<<(unsigned)((n4 + 255) / 256), 256>>>(outp, oh, ol, n4);
        n4 = (size_t)BBATCH * KK * HH / 4;
        split_kernel<<<(unsigned)((n4 + 255) / 256), 256>>>(ctx, ch, cl, n4);
        n4 = (size_t)HH * 2 * HH / 4;
        split_kernel<<<(unsigned)((n4 + 255) / 256), 256>>>(W, wh, wl, n4);
        dim3 grid(KK / 32, HH / 32, BBATCH);
        transpose_split_kernel<<<grid, 256>>>(ctx, cth, ctl);
    }
    // scores (+mask) -> attn region (fp32 logits)
    {
        dim3 grid(KK / 128, QQ / 128, BBATCH);
        gemm_kernel<0><<<grid, 128, SMEM_TOTAL>>>(oh, ol, nullptr, nullptr, ch, cl,
                                                  mask, bias, attn_part, mh, ml, out_part);
    }
    // softmax (emits fp32 attn + hi/lo bf16)
    softmax_kernel<<<BBATCH * QQ, 256>>>(attn_part, ath, atl);
    // mix = attn @ ctx  (emits mix hi/lo bf16)
    {
        dim3 grid(HH / 128, QQ / 128, BBATCH);
        gemm_kernel<1><<<grid, 128, SMEM_TOTAL>>>(ath, atl, nullptr, nullptr, cth, ctl,
                                                  mask, bias, attn_part, mh, ml, out_part);
    }
    // out = tanh([mix|output] @ W^T + b)
    {
        dim3 grid(HH / 128, QQ / 128, BBATCH);
        gemm_kernel<2><<<grid, 128, SMEM_TOTAL>>>(mh, ml, oh, ol, wh, wl,
                                                  mask, bias, attn_part, mh, ml, out_part);
    }
}